// round 2
// baseline (speedup 1.0000x reference)
#include <cuda_runtime.h>
#include <math.h>

#define ADAPTERS 40
#define CAPS 3
#define CLASS_DIM 200
#define IN_CH 600
#define BATCH 256
#define DHID 768

// Scratch (static device arrays -- no allocation at runtime)
__device__ float g_xT[ADAPTERS * IN_CH * BATCH];          // [k][c][b]
__device__ float g_P[CAPS * ADAPTERS * BATCH * CLASS_DIM]; // [n][k][b][d], zero for k>t
__device__ float g_V[CAPS * BATCH * CLASS_DIM];            // [n][b][d] flat

// ---------------------------------------------------------------------------
// f32x2 packed-FMA helpers (sm_103a FFMA2 path; ptxas won't emit from C++)
// ---------------------------------------------------------------------------
__device__ __forceinline__ unsigned long long pk2(float lo, float hi) {
    unsigned long long r;
    asm("mov.b64 %0, {%1, %2};" : "=l"(r) : "f"(lo), "f"(hi));
    return r;
}
__device__ __forceinline__ void ffma2(unsigned long long& c, unsigned long long a, unsigned long long b) {
    asm("fma.rn.f32x2 %0, %1, %2, %0;" : "+l"(c) : "l"(a), "l"(b));
}
__device__ __forceinline__ void unpk2(unsigned long long v, float& lo, float& hi) {
    asm("mov.b64 {%0, %1}, %2;" : "=f"(lo), "=f"(hi) : "l"(v));
}

// ---------------------------------------------------------------------------
// Kernel 0: transpose x (b,k,c) -> xT (k,c,b) so GEMM A-loads coalesce
// ---------------------------------------------------------------------------
__global__ void k_transpose(const float* __restrict__ x) {
    __shared__ float tile[32][33];
    int k = blockIdx.x;
    int c0 = blockIdx.y * 32;
    int b0 = blockIdx.z * 32;
    int tx = threadIdx.x, ty = threadIdx.y;  // (32, 8)
#pragma unroll
    for (int i = 0; i < 4; i++) {
        int b = b0 + ty + i * 8;
        int c = c0 + tx;
        float v = 0.f;
        if (c < IN_CH) v = x[((size_t)b * ADAPTERS + k) * IN_CH + c];
        tile[ty + i * 8][tx] = v;
    }
    __syncthreads();
#pragma unroll
    for (int i = 0; i < 4; i++) {
        int c = c0 + ty + i * 8;
        int b = b0 + tx;
        if (c < IN_CH) g_xT[((size_t)k * IN_CH + c) * BATCH + b] = tile[tx][ty + i * 8];
    }
}

// ---------------------------------------------------------------------------
// Kernel 1: priors GEMM.  For each (k,n):  C[256x200] = A[256x600] B[600x200]
//   A[b][c] = xT[k][c][b]    B[c][d] = rw[k][n][c][d]
// Tiles: BM=128 (b), BN=64 (d), BK=8 (c). 128 threads, 8x8 thread tile,
// accumulators as f32x2 pairs along d (FFMA2 packed fp32 path).
// ---------------------------------------------------------------------------
#define BM 128
#define BN 64
#define BKK 8

__global__ __launch_bounds__(128) void k_gemm(const float* __restrict__ rw,
                                              const int* __restrict__ tptr) {
    int t = *tptr;
    int kn = blockIdx.z;
    int k = kn / 3, n = kn % 3;
    if (k > t) return;  // only k<=t contribute (softmax underflow), uniform exit

    int b0 = blockIdx.x * BM;
    int d0 = blockIdx.y * BN;

    __shared__ float As[BKK][BM];
    __shared__ float Bs[BKK][BN];

    int tid = threadIdx.x;
    int tn = tid & 7;        // 0..7
    int tm = tid >> 3;       // 0..15
    int m0 = tm * 8;
    int n0 = tn * 8;

    unsigned long long acc[8][4];
#pragma unroll
    for (int i = 0; i < 8; i++)
#pragma unroll
        for (int j = 0; j < 4; j++) acc[i][j] = 0ull;

    const float* Abase = g_xT + (size_t)k * IN_CH * BATCH + b0;
    const float* Bbase = rw + (size_t)(k * 3 + n) * IN_CH * CLASS_DIM + d0;

    int lkk = tid >> 4;         // 0..7 (c row within tile)
    int lca = (tid & 15) * 8;   // A col: 0..120
    int lcb = (tid & 15) * 4;   // B col: 0..60
    bool bvalid = (d0 + lcb) < CLASS_DIM;  // 200%4==0 -> whole float4 valid or not

    for (int ct = 0; ct < IN_CH / BKK; ct++) {
        int c0 = ct * BKK;
        float4 a0 = *reinterpret_cast<const float4*>(Abase + (size_t)(c0 + lkk) * BATCH + lca);
        float4 a1 = *reinterpret_cast<const float4*>(Abase + (size_t)(c0 + lkk) * BATCH + lca + 4);
        float4 bv = make_float4(0.f, 0.f, 0.f, 0.f);
        if (bvalid) bv = *reinterpret_cast<const float4*>(Bbase + (size_t)(c0 + lkk) * CLASS_DIM + lcb);

        __syncthreads();
        *reinterpret_cast<float4*>(&As[lkk][lca]) = a0;
        *reinterpret_cast<float4*>(&As[lkk][lca + 4]) = a1;
        *reinterpret_cast<float4*>(&Bs[lkk][lcb]) = bv;
        __syncthreads();

#pragma unroll
        for (int kk = 0; kk < BKK; kk++) {
            const float4 av0 = *reinterpret_cast<const float4*>(&As[kk][m0]);
            const float4 av1 = *reinterpret_cast<const float4*>(&As[kk][m0 + 4]);
            const float4 bv0 = *reinterpret_cast<const float4*>(&Bs[kk][n0]);
            const float4 bv1 = *reinterpret_cast<const float4*>(&Bs[kk][n0 + 4]);
            unsigned long long bp[4];
            bp[0] = pk2(bv0.x, bv0.y);
            bp[1] = pk2(bv0.z, bv0.w);
            bp[2] = pk2(bv1.x, bv1.y);
            bp[3] = pk2(bv1.z, bv1.w);
            float am[8] = {av0.x, av0.y, av0.z, av0.w, av1.x, av1.y, av1.z, av1.w};
#pragma unroll
            for (int i = 0; i < 8; i++) {
                unsigned long long ap = pk2(am[i], am[i]);
#pragma unroll
                for (int j = 0; j < 4; j++) ffma2(acc[i][j], ap, bp[j]);
            }
        }
    }

    float* Cbase = g_P + (((size_t)(n * ADAPTERS + k) * BATCH + b0)) * CLASS_DIM + d0;
#pragma unroll
    for (int i = 0; i < 8; i++) {
        int m = m0 + i;
#pragma unroll
        for (int j = 0; j < 2; j++) {
            int d = n0 + j * 4;
            if (d0 + d < CLASS_DIM) {
                float4 o;
                unpk2(acc[i][2 * j], o.x, o.y);
                unpk2(acc[i][2 * j + 1], o.z, o.w);
                *reinterpret_cast<float4*>(Cbase + (size_t)m * CLASS_DIM + d) = o;
            }
        }
    }
}

// ---------------------------------------------------------------------------
// Kernel 2: dynamic routing per (n, b). Logits are constant over d, so they
// collapse to 40-vectors. 3 iterations, final vote written to g_V.
// ---------------------------------------------------------------------------
__global__ __launch_bounds__(256) void k_route(const int* __restrict__ tptr,
                                               const float* __restrict__ tsv) {
    __shared__ float Ps[ADAPTERS][CLASS_DIM];
    __shared__ float tsvv[ADAPTERS], maskv[ADAPTERS];
    __shared__ float l[ADAPTERS], probs[ADAPTERS], leff[ADAPTERS];
    __shared__ float vote[CLASS_DIM], outv[CLASS_DIM];
    __shared__ float coef_s;

    int b = blockIdx.x, n = blockIdx.y;
    int tid = threadIdx.x;
    int t = *tptr;

    const float* Pb = g_P + ((size_t)(n * ADAPTERS) * BATCH + b) * CLASS_DIM;
    for (int idx = tid; idx < ADAPTERS * CLASS_DIM; idx += 256) {
        int k = idx / CLASS_DIM, d = idx - k * CLASS_DIM;
        Ps[k][d] = Pb[(size_t)k * BATCH * CLASS_DIM + d];
    }
    if (tid < ADAPTERS) {
        float tv = tsv[t * ADAPTERS + tid];
        tsvv[tid] = tv;
        maskv[tid] = (tv == 0.f) ? -10000.f : 0.f;
        l[tid] = 0.f;
    }
    __syncthreads();

    for (int it = 0; it < 3; it++) {
        if (tid < ADAPTERS) leff[tid] = l[tid] * tsvv[tid] + maskv[tid];
        __syncthreads();
        if (tid == 0) {
            float mx = leff[0];
            for (int kk = 1; kk < ADAPTERS; kk++) mx = fmaxf(mx, leff[kk]);
            float sm = 0.f;
            for (int kk = 0; kk < ADAPTERS; kk++) {
                float e = expf(leff[kk] - mx);
                probs[kk] = e;
                sm += e;
            }
            float inv = 1.f / sm;
            for (int kk = 0; kk < ADAPTERS; kk++) probs[kk] *= inv;
        }
        __syncthreads();
        if (tid < CLASS_DIM) {
            float v = 0.f;
#pragma unroll 8
            for (int kk = 0; kk < ADAPTERS; kk++) v += probs[kk] * Ps[kk][tid];
            vote[tid] = v;
        }
        __syncthreads();
        if (it == 2) break;

        // squash coefficient: sqrt(sq)/(1+sq)
        if (tid < 32) {
            float p = 0.f;
            for (int d = tid; d < CLASS_DIM; d += 32) {
                float v = vote[d];
                p += v * v;
            }
            for (int o = 16; o > 0; o >>= 1) p += __shfl_down_sync(0xffffffff, p, o);
            if (tid == 0) {
                float sq = p;
                coef_s = sqrtf(sq) / (1.f + sq);
            }
        }
        __syncthreads();
        if (tid < CLASS_DIM) outv[tid] = vote[tid] * coef_s;
        __syncthreads();

        // agreement a[k] = dot(Ps[k], out) -> l[k] += a[k]
        int w = tid >> 5, lane = tid & 31;
        for (int kk = w; kk < ADAPTERS; kk += 8) {
            float p = 0.f;
            for (int d = lane; d < CLASS_DIM; d += 32) p += Ps[kk][d] * outv[d];
            for (int o = 16; o > 0; o >>= 1) p += __shfl_down_sync(0xffffffff, p, o);
            if (lane == 0) l[kk] += p;
        }
        __syncthreads();
    }

    if (tid < CLASS_DIM) g_V[((size_t)n * BATCH + b) * CLASS_DIM + tid] = vote[tid];
}

// ---------------------------------------------------------------------------
// Kernel 3: expansion. h slice per b2 is a contiguous 600-float span of g_V
// (reshape (n,b,d)->(b2,d2,c2) is flat-order preserving per b2).
// out[b2,d2,j] = (h0*W[j,0]+h1*W[j,1]+h2*W[j,2] + bias[j]) * sigmoid(s*el[t,j])
// Write-bound: 157 MB of float4 stores.
// ---------------------------------------------------------------------------
__global__ __launch_bounds__(256) void k_expand(const int* __restrict__ tptr,
                                                const float* __restrict__ s_ptr,
                                                const float* __restrict__ W,
                                                const float* __restrict__ bvec,
                                                const float* __restrict__ el,
                                                float* __restrict__ out) {
    __shared__ float h[CLASS_DIM * CAPS];   // 600
    __shared__ float4 coef[DHID];           // {g*w0, g*w1, g*w2, g*b}

    int b2 = blockIdx.x, tid = threadIdx.x;
    int t = *tptr;
    float s = s_ptr[0];

    for (int idx = tid; idx < CLASS_DIM * CAPS; idx += 256)
        h[idx] = g_V[(size_t)b2 * (CLASS_DIM * CAPS) + idx];
    for (int j = tid; j < DHID; j += 256) {
        float e = el[(size_t)t * DHID + j];
        float g = 1.f / (1.f + expf(-s * e));
        coef[j] = make_float4(W[j * 3 + 0] * g, W[j * 3 + 1] * g, W[j * 3 + 2] * g,
                              bvec[j] * g);
    }
    __syncthreads();

    float* ob = out + (size_t)b2 * CLASS_DIM * DHID;
#pragma unroll 4
    for (int it = 0; it < (CLASS_DIM * DHID) / 1024; it++) {
        int base = (it * 256 + tid) * 4;
        int d2 = base / DHID;
        int j = base - d2 * DHID;
        float h0 = h[d2 * 3], h1 = h[d2 * 3 + 1], h2 = h[d2 * 3 + 2];
        float4 c0 = coef[j], c1 = coef[j + 1], c2 = coef[j + 2], c3 = coef[j + 3];
        float4 o;
        o.x = h0 * c0.x + h1 * c0.y + h2 * c0.z + c0.w;
        o.y = h0 * c1.x + h1 * c1.y + h2 * c1.z + c1.w;
        o.z = h0 * c2.x + h1 * c2.y + h2 * c2.z + c2.w;
        o.w = h0 * c3.x + h1 * c3.y + h2 * c3.z + c3.w;
        *reinterpret_cast<float4*>(ob + base) = o;
    }
}

// ---------------------------------------------------------------------------
extern "C" void kernel_launch(void* const* d_in, const int* in_sizes, int n_in,
                              void* d_out, int out_size) {
    const int* t = (const int*)d_in[0];
    const float* x = (const float*)d_in[1];
    const float* s = (const float*)d_in[2];
    const float* rw = (const float*)d_in[3];
    const float* W = (const float*)d_in[4];
    const float* bb = (const float*)d_in[5];
    const float* el = (const float*)d_in[6];
    const float* tsv = (const float*)d_in[7];
    float* out = (float*)d_out;

    k_transpose<<<dim3(ADAPTERS, (IN_CH + 31) / 32, BATCH / 32), dim3(32, 8)>>>(x);
    k_gemm<<<dim3(BATCH / BM, (CLASS_DIM + BN - 1) / BN, ADAPTERS * CAPS), 128>>>(rw, t);
    k_route<<<dim3(BATCH, CAPS), 256>>>(t, tsv);
    k_expand<<<BATCH, 256>>>(t, s, W, bb, el, out);
}

// round 3
// speedup vs baseline: 1.2737x; 1.2737x over previous
#include <cuda_runtime.h>
#include <math.h>

#define ADAPTERS 40
#define CAPS 3
#define CLASS_DIM 200
#define IN_CH 600
#define BATCH 256
#define DHID 768

// Scratch (static device arrays -- no allocation at runtime)
__device__ float g_xT[ADAPTERS * IN_CH * BATCH];          // [k][c][b]
__device__ float g_P[CAPS * ADAPTERS * BATCH * CLASS_DIM]; // [n][k][b][d], zero for k>t
__device__ float g_V[CAPS * BATCH * CLASS_DIM];            // [n][b][d] flat

// ---------------------------------------------------------------------------
// f32x2 packed-FMA helpers (sm_103a FFMA2 path; ptxas won't emit from C++)
// ---------------------------------------------------------------------------
__device__ __forceinline__ unsigned long long pk2(float lo, float hi) {
    unsigned long long r;
    asm("mov.b64 %0, {%1, %2};" : "=l"(r) : "f"(lo), "f"(hi));
    return r;
}
__device__ __forceinline__ void ffma2(unsigned long long& c, unsigned long long a, unsigned long long b) {
    asm("fma.rn.f32x2 %0, %1, %2, %0;" : "+l"(c) : "l"(a), "l"(b));
}
__device__ __forceinline__ void unpk2(unsigned long long v, float& lo, float& hi) {
    asm("mov.b64 {%0, %1}, %2;" : "=f"(lo), "=f"(hi) : "l"(v));
}

// ---------------------------------------------------------------------------
// Kernel 0: transpose x (b,k,c) -> xT (k,c,b) so GEMM A-loads coalesce
// ---------------------------------------------------------------------------
__global__ void k_transpose(const float* __restrict__ x) {
    __shared__ float tile[32][33];
    int k = blockIdx.x;
    int c0 = blockIdx.y * 32;
    int b0 = blockIdx.z * 32;
    int tx = threadIdx.x, ty = threadIdx.y;  // (32, 8)
#pragma unroll
    for (int i = 0; i < 4; i++) {
        int b = b0 + ty + i * 8;
        int c = c0 + tx;
        float v = 0.f;
        if (c < IN_CH) v = x[((size_t)b * ADAPTERS + k) * IN_CH + c];
        tile[ty + i * 8][tx] = v;
    }
    __syncthreads();
#pragma unroll
    for (int i = 0; i < 4; i++) {
        int c = c0 + ty + i * 8;
        int b = b0 + tx;
        if (c < IN_CH) g_xT[((size_t)k * IN_CH + c) * BATCH + b] = tile[tx][ty + i * 8];
    }
}

// ---------------------------------------------------------------------------
// Kernel 1: priors GEMM with LDG->compute overlap (prefetch next tile's
// global loads before the FFMA2 block so their latency hides under compute).
// For each (k,n):  C[256x200] = A[256x600] B[600x200]
// Tiles: BM=128 (b), BN=64 (d), BK=8 (c). 128 threads, 8x8 thread tile.
// ---------------------------------------------------------------------------
#define BM 128
#define BN 64
#define BKK 8
#define NTILES (IN_CH / BKK)

__global__ __launch_bounds__(128) void k_gemm(const float* __restrict__ rw,
                                              const int* __restrict__ tptr) {
    int t = *tptr;
    int kn = blockIdx.z;
    int k = kn / 3, n = kn % 3;
    if (k > t) return;  // only k<=t contribute (softmax underflow), uniform exit

    int b0 = blockIdx.x * BM;
    int d0 = blockIdx.y * BN;

    __shared__ float As[BKK][BM];
    __shared__ float Bs[BKK][BN];

    int tid = threadIdx.x;
    int tn = tid & 7;        // 0..7
    int tm = tid >> 3;       // 0..15
    int m0 = tm * 8;
    int n0 = tn * 8;

    unsigned long long acc[8][4];
#pragma unroll
    for (int i = 0; i < 8; i++)
#pragma unroll
        for (int j = 0; j < 4; j++) acc[i][j] = 0ull;

    const float* Abase = g_xT + (size_t)k * IN_CH * BATCH + b0;
    const float* Bbase = rw + (size_t)(k * 3 + n) * IN_CH * CLASS_DIM + d0;

    int lkk = tid >> 4;         // 0..7 (c row within tile)
    int lca = (tid & 15) * 8;   // A col: 0..120
    int lcb = (tid & 15) * 4;   // B col: 0..60
    bool bvalid = (d0 + lcb) < CLASS_DIM;  // 200%4==0 -> whole float4 valid or not

    const float* Aptr = Abase + (size_t)lkk * BATCH + lca;
    const float* Bptr = Bbase + (size_t)lkk * CLASS_DIM + lcb;

    // Prologue: load tile 0
    float4 a0 = *reinterpret_cast<const float4*>(Aptr);
    float4 a1 = *reinterpret_cast<const float4*>(Aptr + 4);
    float4 bv = make_float4(0.f, 0.f, 0.f, 0.f);
    if (bvalid) bv = *reinterpret_cast<const float4*>(Bptr);
    Aptr += BKK * BATCH;
    Bptr += BKK * CLASS_DIM;

    for (int ct = 0; ct < NTILES; ct++) {
        __syncthreads();
        *reinterpret_cast<float4*>(&As[lkk][lca]) = a0;
        *reinterpret_cast<float4*>(&As[lkk][lca + 4]) = a1;
        *reinterpret_cast<float4*>(&Bs[lkk][lcb]) = bv;
        __syncthreads();

        // Prefetch next tile's global loads: latency hides under compute below
        if (ct + 1 < NTILES) {
            a0 = *reinterpret_cast<const float4*>(Aptr);
            a1 = *reinterpret_cast<const float4*>(Aptr + 4);
            if (bvalid) bv = *reinterpret_cast<const float4*>(Bptr);
            Aptr += BKK * BATCH;
            Bptr += BKK * CLASS_DIM;
        }

#pragma unroll
        for (int kk = 0; kk < BKK; kk++) {
            const float4 av0 = *reinterpret_cast<const float4*>(&As[kk][m0]);
            const float4 av1 = *reinterpret_cast<const float4*>(&As[kk][m0 + 4]);
            const float4 bv0 = *reinterpret_cast<const float4*>(&Bs[kk][n0]);
            const float4 bv1 = *reinterpret_cast<const float4*>(&Bs[kk][n0 + 4]);
            unsigned long long bp[4];
            bp[0] = pk2(bv0.x, bv0.y);
            bp[1] = pk2(bv0.z, bv0.w);
            bp[2] = pk2(bv1.x, bv1.y);
            bp[3] = pk2(bv1.z, bv1.w);
            float am[8] = {av0.x, av0.y, av0.z, av0.w, av1.x, av1.y, av1.z, av1.w};
#pragma unroll
            for (int i = 0; i < 8; i++) {
                unsigned long long ap = pk2(am[i], am[i]);
#pragma unroll
                for (int j = 0; j < 4; j++) ffma2(acc[i][j], ap, bp[j]);
            }
        }
    }

    float* Cbase = g_P + (((size_t)(n * ADAPTERS + k) * BATCH + b0)) * CLASS_DIM + d0;
#pragma unroll
    for (int i = 0; i < 8; i++) {
        int m = m0 + i;
#pragma unroll
        for (int j = 0; j < 2; j++) {
            int d = n0 + j * 4;
            if (d0 + d < CLASS_DIM) {
                float4 o;
                unpk2(acc[i][2 * j], o.x, o.y);
                unpk2(acc[i][2 * j + 1], o.z, o.w);
                *reinterpret_cast<float4*>(Cbase + (size_t)m * CLASS_DIM + d) = o;
            }
        }
    }
}

// ---------------------------------------------------------------------------
// Kernel 2: dynamic routing per (n, b). Logits are constant over d, so they
// collapse to 40-vectors. 3 iterations, final vote written to g_V.
// ---------------------------------------------------------------------------
__global__ __launch_bounds__(256) void k_route(const int* __restrict__ tptr,
                                               const float* __restrict__ tsv) {
    __shared__ float Ps[ADAPTERS][CLASS_DIM];
    __shared__ float tsvv[ADAPTERS], maskv[ADAPTERS];
    __shared__ float l[ADAPTERS], probs[ADAPTERS], leff[ADAPTERS];
    __shared__ float vote[CLASS_DIM], outv[CLASS_DIM];
    __shared__ float coef_s;

    int b = blockIdx.x, n = blockIdx.y;
    int tid = threadIdx.x;
    int t = *tptr;

    const float* Pb = g_P + ((size_t)(n * ADAPTERS) * BATCH + b) * CLASS_DIM;
    for (int idx = tid; idx < ADAPTERS * CLASS_DIM; idx += 256) {
        int k = idx / CLASS_DIM, d = idx - k * CLASS_DIM;
        Ps[k][d] = Pb[(size_t)k * BATCH * CLASS_DIM + d];
    }
    if (tid < ADAPTERS) {
        float tv = tsv[t * ADAPTERS + tid];
        tsvv[tid] = tv;
        maskv[tid] = (tv == 0.f) ? -10000.f : 0.f;
        l[tid] = 0.f;
    }
    __syncthreads();

    for (int it = 0; it < 3; it++) {
        if (tid < ADAPTERS) leff[tid] = l[tid] * tsvv[tid] + maskv[tid];
        __syncthreads();
        if (tid == 0) {
            float mx = leff[0];
            for (int kk = 1; kk < ADAPTERS; kk++) mx = fmaxf(mx, leff[kk]);
            float sm = 0.f;
            for (int kk = 0; kk < ADAPTERS; kk++) {
                float e = expf(leff[kk] - mx);
                probs[kk] = e;
                sm += e;
            }
            float inv = 1.f / sm;
            for (int kk = 0; kk < ADAPTERS; kk++) probs[kk] *= inv;
        }
        __syncthreads();
        if (tid < CLASS_DIM) {
            float v = 0.f;
#pragma unroll 8
            for (int kk = 0; kk < ADAPTERS; kk++) v += probs[kk] * Ps[kk][tid];
            vote[tid] = v;
        }
        __syncthreads();
        if (it == 2) break;

        // squash coefficient: sqrt(sq)/(1+sq)
        if (tid < 32) {
            float p = 0.f;
            for (int d = tid; d < CLASS_DIM; d += 32) {
                float v = vote[d];
                p += v * v;
            }
            for (int o = 16; o > 0; o >>= 1) p += __shfl_down_sync(0xffffffff, p, o);
            if (tid == 0) {
                float sq = p;
                coef_s = sqrtf(sq) / (1.f + sq);
            }
        }
        __syncthreads();
        if (tid < CLASS_DIM) outv[tid] = vote[tid] * coef_s;
        __syncthreads();

        // agreement a[k] = dot(Ps[k], out) -> l[k] += a[k]
        int w = tid >> 5, lane = tid & 31;
        for (int kk = w; kk < ADAPTERS; kk += 8) {
            float p = 0.f;
            for (int d = lane; d < CLASS_DIM; d += 32) p += Ps[kk][d] * outv[d];
            for (int o = 16; o > 0; o >>= 1) p += __shfl_down_sync(0xffffffff, p, o);
            if (lane == 0) l[kk] += p;
        }
        __syncthreads();
    }

    if (tid < CLASS_DIM) g_V[((size_t)n * BATCH + b) * CLASS_DIM + tid] = vote[tid];
}

// ---------------------------------------------------------------------------
// Kernel 3: expansion, v2. Register-resident gated coefficients: thread tid
// owns j = tid*4..tid*4+3 (192 threads cover DHID=768), loops over 50 d2 rows.
// Per float4 store: 3 broadcast LDS + 12 FFMA + 1 STG.128. No div/mod, no
// per-element coef LDS. Grid (BATCH, 4) for 3x the occupancy.
// ---------------------------------------------------------------------------
#define EXP_SPLIT 4
#define EXP_ROWS (CLASS_DIM / EXP_SPLIT)  // 50

__global__ __launch_bounds__(192) void k_expand(const int* __restrict__ tptr,
                                                const float* __restrict__ s_ptr,
                                                const float* __restrict__ W,
                                                const float* __restrict__ bvec,
                                                const float* __restrict__ el,
                                                float* __restrict__ out) {
    __shared__ float h[CLASS_DIM * CAPS];   // 600

    int b2 = blockIdx.x;
    int d2_0 = blockIdx.y * EXP_ROWS;
    int tid = threadIdx.x;
    int t = *tptr;
    float s = s_ptr[0];

    for (int idx = tid; idx < CLASS_DIM * CAPS; idx += 192)
        h[idx] = g_V[(size_t)b2 * (CLASS_DIM * CAPS) + idx];

    int j = tid * 4;
    float4 e4 = *reinterpret_cast<const float4*>(el + (size_t)t * DHID + j);
    float4 b4 = *reinterpret_cast<const float4*>(bvec + j);
    float g0 = 1.f / (1.f + expf(-s * e4.x));
    float g1 = 1.f / (1.f + expf(-s * e4.y));
    float g2 = 1.f / (1.f + expf(-s * e4.z));
    float g3 = 1.f / (1.f + expf(-s * e4.w));
    // W is [DHID][3]; j*3 = tid*12 is float4-aligned
    float4 w0 = *reinterpret_cast<const float4*>(W + j * 3);
    float4 w1 = *reinterpret_cast<const float4*>(W + j * 3 + 4);
    float4 w2 = *reinterpret_cast<const float4*>(W + j * 3 + 8);
    float4 c0 = make_float4(w0.x * g0, w0.y * g0, w0.z * g0, b4.x * g0);
    float4 c1 = make_float4(w0.w * g1, w1.x * g1, w1.y * g1, b4.y * g1);
    float4 c2 = make_float4(w1.z * g2, w1.w * g2, w2.x * g2, b4.z * g2);
    float4 c3 = make_float4(w2.y * g3, w2.z * g3, w2.w * g3, b4.w * g3);
    __syncthreads();

    float* ob = out + (size_t)b2 * CLASS_DIM * DHID + (size_t)d2_0 * DHID + j;
    const float* hp = h + d2_0 * 3;
#pragma unroll 2
    for (int r = 0; r < EXP_ROWS; r++) {
        float h0 = hp[0], h1 = hp[1], h2 = hp[2];
        hp += 3;
        float4 o;
        o.x = fmaf(h0, c0.x, fmaf(h1, c0.y, fmaf(h2, c0.z, c0.w)));
        o.y = fmaf(h0, c1.x, fmaf(h1, c1.y, fmaf(h2, c1.z, c1.w)));
        o.z = fmaf(h0, c2.x, fmaf(h1, c2.y, fmaf(h2, c2.z, c2.w)));
        o.w = fmaf(h0, c3.x, fmaf(h1, c3.y, fmaf(h2, c3.z, c3.w)));
        *reinterpret_cast<float4*>(ob) = o;
        ob += DHID;
    }
}

// ---------------------------------------------------------------------------
extern "C" void kernel_launch(void* const* d_in, const int* in_sizes, int n_in,
                              void* d_out, int out_size) {
    const int* t = (const int*)d_in[0];
    const float* x = (const float*)d_in[1];
    const float* s = (const float*)d_in[2];
    const float* rw = (const float*)d_in[3];
    const float* W = (const float*)d_in[4];
    const float* bb = (const float*)d_in[5];
    const float* el = (const float*)d_in[6];
    const float* tsv = (const float*)d_in[7];
    float* out = (float*)d_out;

    k_transpose<<<dim3(ADAPTERS, (IN_CH + 31) / 32, BATCH / 32), dim3(32, 8)>>>(x);
    k_gemm<<<dim3(BATCH / BM, (CLASS_DIM + BN - 1) / BN, ADAPTERS * CAPS), 128>>>(rw, t);
    k_route<<<dim3(BATCH, CAPS), 256>>>(t, tsv);
    k_expand<<<dim3(BATCH, EXP_SPLIT), 192>>>(t, s, W, bb, el, out);
}